// round 5
// baseline (speedup 1.0000x reference)
#include <cuda_runtime.h>
#include <cuda_bf16.h>
#include <cstdint>
#include <cstddef>

#define B_   32
#define S_   2048
#define D_   256
#define G3_  768

// gi scratch: [dir][b][s][768]  (402 MB, fully rewritten every call)
__device__ float g_gi[(size_t)2 * B_ * S_ * G3_];

// ---------------------------------------------------------------------------
// Kernel 1: gi[dir][m][n] = V[m][:] . W_ih(dir)[n][:] + b_ih[n]
// M = B*S = 65536, N = 768, K = 256.  128x128x8 fp32 SGEMM, 256 thr, 8x8 micro.
// ---------------------------------------------------------------------------
__global__ __launch_bounds__(256, 2) void gi_gemm(
    const float* __restrict__ V,
    const float* __restrict__ Wf, const float* __restrict__ Wb,
    const float* __restrict__ bf, const float* __restrict__ bb)
{
    const int dir = blockIdx.z;
    const float* __restrict__ W   = dir ? Wb : Wf;
    const float* __restrict__ bih = dir ? bb : bf;
    const int m0 = blockIdx.x * 128;
    const int n0 = blockIdx.y * 128;

    __shared__ float As[2][8][132];   // pad 128->132: conflict-free stores
    __shared__ float Bs[2][8][132];

    const int tid = threadIdx.x;
    const int lr  = tid >> 1;          // 0..127
    const int lk  = (tid & 1) * 4;     // 0 or 4

    const float* aptr = V + (size_t)(m0 + lr) * 256 + lk;
    const float* bptr = W + (size_t)(n0 + lr) * 256 + lk;

    const int tx = tid & 15;
    const int ty = tid >> 4;

    float acc[8][8];
#pragma unroll
    for (int i = 0; i < 8; i++)
#pragma unroll
        for (int j = 0; j < 8; j++) acc[i][j] = 0.f;

    float4 a = *(const float4*)aptr;
    float4 b = *(const float4*)bptr;
    As[0][lk + 0][lr] = a.x; As[0][lk + 1][lr] = a.y;
    As[0][lk + 2][lr] = a.z; As[0][lk + 3][lr] = a.w;
    Bs[0][lk + 0][lr] = b.x; Bs[0][lk + 1][lr] = b.y;
    Bs[0][lk + 2][lr] = b.z; Bs[0][lk + 3][lr] = b.w;
    __syncthreads();

    int cur = 0;
    for (int kt = 0; kt < 32; kt++) {
        if (kt < 31) {
            a = *(const float4*)(aptr + (kt + 1) * 8);
            b = *(const float4*)(bptr + (kt + 1) * 8);
        }
#pragma unroll
        for (int k = 0; k < 8; k++) {
            float4 a0 = *(const float4*)&As[cur][k][ty * 8];
            float4 a1 = *(const float4*)&As[cur][k][ty * 8 + 4];
            float4 b0 = *(const float4*)&Bs[cur][k][tx * 8];
            float4 b1 = *(const float4*)&Bs[cur][k][tx * 8 + 4];
            float av[8] = {a0.x, a0.y, a0.z, a0.w, a1.x, a1.y, a1.z, a1.w};
            float bv[8] = {b0.x, b0.y, b0.z, b0.w, b1.x, b1.y, b1.z, b1.w};
#pragma unroll
            for (int i = 0; i < 8; i++)
#pragma unroll
                for (int j = 0; j < 8; j++)
                    acc[i][j] = fmaf(av[i], bv[j], acc[i][j]);
        }
        if (kt < 31) {
            const int nxt = cur ^ 1;
            As[nxt][lk + 0][lr] = a.x; As[nxt][lk + 1][lr] = a.y;
            As[nxt][lk + 2][lr] = a.z; As[nxt][lk + 3][lr] = a.w;
            Bs[nxt][lk + 0][lr] = b.x; Bs[nxt][lk + 1][lr] = b.y;
            Bs[nxt][lk + 2][lr] = b.z; Bs[nxt][lk + 3][lr] = b.w;
            __syncthreads();
            cur = nxt;
        }
    }

    float bias[8];
#pragma unroll
    for (int j = 0; j < 8; j++) bias[j] = bih[n0 + tx * 8 + j];

    float* gout = g_gi + (size_t)dir * B_ * S_ * G3_;
#pragma unroll
    for (int i = 0; i < 8; i++) {
        const size_t row = (size_t)(m0 + ty * 8 + i);
        float4 o0, o1;
        o0.x = acc[i][0] + bias[0]; o0.y = acc[i][1] + bias[1];
        o0.z = acc[i][2] + bias[2]; o0.w = acc[i][3] + bias[3];
        o1.x = acc[i][4] + bias[4]; o1.y = acc[i][5] + bias[5];
        o1.z = acc[i][6] + bias[6]; o1.w = acc[i][7] + bias[7];
        *(float4*)(gout + row * G3_ + n0 + tx * 8)     = o0;
        *(float4*)(gout + row * G3_ + n0 + tx * 8 + 4) = o1;
    }
}

// ---------------------------------------------------------------------------
// Kernel 2: GRU recurrence, both directions.
// Cluster of 4 CTAs = one (dir, batch-pair). CTA rank owns hidden units
// [rank*64, rank*64+64): 192 w_hh rows held in registers. h double-buffered in
// SMEM, replicated across the cluster with st.shared::cluster; one
// barrier.cluster per step. thread: jl = tid>>2 (unit), ks = tid&3 (K-slice).
// grid = (4, 16, 2) = 128 CTAs x 256 thr.
// ---------------------------------------------------------------------------
__device__ __forceinline__ uint32_t smem_u32(const void* p) {
    uint32_t a;
    asm("{ .reg .u64 t; cvta.to.shared.u64 t, %1; cvt.u32.u64 %0, t; }"
        : "=r"(a) : "l"(p));
    return a;
}

__device__ __forceinline__ float sigm(float x) {
    return 1.f / (1.f + __expf(-x));
}

__global__ void __cluster_dims__(4, 1, 1) __launch_bounds__(256, 1)
rnn_rec(const float* __restrict__ whhf, const float* __restrict__ whhb,
        const float* __restrict__ bhhf, const float* __restrict__ bhhb,
        const float* __restrict__ V, float* __restrict__ out,
        int cl, int T)
{
    __shared__ float hbuf[2][2][256];   // [phase][batch][hidden]

    const int tid = threadIdx.x;
    const int jl  = tid >> 2;
    const int ks  = tid & 3;
    unsigned rank;
    asm("mov.u32 %0, %%cluster_ctarank;" : "=r"(rank));
    const int j   = (int)rank * 64 + jl;
    const int dir = blockIdx.z;
    const int b0  = blockIdx.y * 2;

    const float* __restrict__ WHH = dir ? whhb : whhf;
    const float* __restrict__ BHH = dir ? bhhb : bhhf;

    // Register-resident weight slice; chunk order XOR-swizzled by ks so the
    // four K-slice lanes of a quad read disjoint SMEM bank groups.
    float wr[64], wz[64], wn[64];
    {
        const float* pr = WHH + (size_t)(      j) * 256 + ks * 64;
        const float* pz = WHH + (size_t)(256 + j) * 256 + ks * 64;
        const float* pn = WHH + (size_t)(512 + j) * 256 + ks * 64;
#pragma unroll
        for (int i = 0; i < 16; i++) {
            const int ci = (i ^ (ks << 1)) & 15;
            float4 q;
            q = *(const float4*)(pr + ci * 4);
            wr[4*i+0]=q.x; wr[4*i+1]=q.y; wr[4*i+2]=q.z; wr[4*i+3]=q.w;
            q = *(const float4*)(pz + ci * 4);
            wz[4*i+0]=q.x; wz[4*i+1]=q.y; wz[4*i+2]=q.z; wz[4*i+3]=q.w;
            q = *(const float4*)(pn + ci * 4);
            wn[4*i+0]=q.x; wn[4*i+1]=q.y; wn[4*i+2]=q.z; wn[4*i+3]=q.w;
        }
    }
    const float br = BHH[j], bz = BHH[256 + j], bn = BHH[512 + j];

    // zero h phase 0 (512 floats)
    if (tid < 128) ((float4*)&hbuf[0][0][0])[tid] = make_float4(0.f, 0.f, 0.f, 0.f);
    __syncthreads();
    asm volatile("barrier.cluster.arrive.aligned;" ::: "memory");
    asm volatile("barrier.cluster.wait.aligned;"   ::: "memory");

    const uint32_t hb = smem_u32(&hbuf[0][0][0]);

    // Lanes ks==0 / ks==1 own the gate math for batch 0 / 1 respectively.
    const int s0 = dir ? (S_ - 1) : 0;
    const ptrdiff_t gstep = dir ? -(ptrdiff_t)G3_ : (ptrdiff_t)G3_;
    const ptrdiff_t vstep = dir ? -(ptrdiff_t)256 : (ptrdiff_t)256;
    const int bb = ks & 1;

    const float* gi_my = g_gi + ((size_t)dir * B_ + b0 + bb) * S_ * G3_
                              + (size_t)s0 * G3_ + j;
    const float* v_my  = V + ((size_t)(b0 + bb) * S_ + s0) * 256 + j;
    float* o_my        = out + (size_t)(b0 + bb) * T * 512 + (size_t)dir * 256 + j;

    float g_r = 0.f, g_z = 0.f, g_n = 0.f, vv = 0.f, hp = 0.f;

    for (int step = 0; step < S_; ++step) {
        const int p = step & 1;
        const float* hs = &hbuf[p][0][0];

        // early loads (only gate-owner lanes) — hidden under the FMA phase
        if (ks < 2) {
            g_r = gi_my[0];
            g_z = gi_my[256];
            g_n = gi_my[512];
            vv  = v_my[0];
            hp  = hs[bb * 256 + j];
        }

        // --- gh partial dot products: 2 batches x 3 gates x 64 K ---
        float ar0 = 0.f, az0 = 0.f, an0 = 0.f;
        float ar1 = 0.f, az1 = 0.f, an1 = 0.f;
        const float* h0 = hs + ks * 64;
        const float* h1 = hs + 256 + ks * 64;
#pragma unroll
        for (int i = 0; i < 16; i++) {
            const int ci = (i ^ (ks << 1)) & 15;
            float4 hv = *(const float4*)(h0 + 4 * ci);
            ar0 = fmaf(wr[4*i+0], hv.x, ar0); ar0 = fmaf(wr[4*i+1], hv.y, ar0);
            ar0 = fmaf(wr[4*i+2], hv.z, ar0); ar0 = fmaf(wr[4*i+3], hv.w, ar0);
            az0 = fmaf(wz[4*i+0], hv.x, az0); az0 = fmaf(wz[4*i+1], hv.y, az0);
            az0 = fmaf(wz[4*i+2], hv.z, az0); az0 = fmaf(wz[4*i+3], hv.w, az0);
            an0 = fmaf(wn[4*i+0], hv.x, an0); an0 = fmaf(wn[4*i+1], hv.y, an0);
            an0 = fmaf(wn[4*i+2], hv.z, an0); an0 = fmaf(wn[4*i+3], hv.w, an0);
        }
#pragma unroll
        for (int i = 0; i < 16; i++) {
            const int ci = (i ^ (ks << 1)) & 15;
            float4 hv = *(const float4*)(h1 + 4 * ci);
            ar1 = fmaf(wr[4*i+0], hv.x, ar1); ar1 = fmaf(wr[4*i+1], hv.y, ar1);
            ar1 = fmaf(wr[4*i+2], hv.z, ar1); ar1 = fmaf(wr[4*i+3], hv.w, ar1);
            az1 = fmaf(wz[4*i+0], hv.x, az1); az1 = fmaf(wz[4*i+1], hv.y, az1);
            az1 = fmaf(wz[4*i+2], hv.z, az1); az1 = fmaf(wz[4*i+3], hv.w, az1);
            an1 = fmaf(wn[4*i+0], hv.x, an1); an1 = fmaf(wn[4*i+1], hv.y, an1);
            an1 = fmaf(wn[4*i+2], hv.z, an1); an1 = fmaf(wn[4*i+3], hv.w, an1);
        }

        // --- quad butterfly reduce (all lanes get full sums) ---
        ar0 += __shfl_xor_sync(0xffffffffu, ar0, 1, 4);
        ar0 += __shfl_xor_sync(0xffffffffu, ar0, 2, 4);
        az0 += __shfl_xor_sync(0xffffffffu, az0, 1, 4);
        az0 += __shfl_xor_sync(0xffffffffu, az0, 2, 4);
        an0 += __shfl_xor_sync(0xffffffffu, an0, 1, 4);
        an0 += __shfl_xor_sync(0xffffffffu, an0, 2, 4);
        ar1 += __shfl_xor_sync(0xffffffffu, ar1, 1, 4);
        ar1 += __shfl_xor_sync(0xffffffffu, ar1, 2, 4);
        az1 += __shfl_xor_sync(0xffffffffu, az1, 1, 4);
        az1 += __shfl_xor_sync(0xffffffffu, az1, 2, 4);
        an1 += __shfl_xor_sync(0xffffffffu, an1, 1, 4);
        an1 += __shfl_xor_sync(0xffffffffu, an1, 2, 4);

        if (ks < 2) {
            const float ar = bb ? ar1 : ar0;
            const float az = bb ? az1 : az0;
            const float an = bb ? an1 : an0;

            const float r = sigm(g_r + ar + br);
            const float z = sigm(g_z + az + bz);
            const float n = tanhf(g_n + r * (an + bn));
            const float hn = (1.f - z) * n + z * hp;

            // replicate h' into every cluster CTA's next-phase buffer
            const uint32_t la = hb + 4u * (uint32_t)(((p ^ 1) * 2 + bb) * 256 + j);
#pragma unroll
            for (int rdst = 0; rdst < 4; rdst++) {
                uint32_t ra;
                asm("mapa.shared::cluster.u32 %0, %1, %2;"
                    : "=r"(ra) : "r"(la), "r"(rdst));
                asm volatile("st.shared::cluster.f32 [%0], %1;"
                             :: "r"(ra), "f"(hn) : "memory");
            }

            if ((unsigned)(step - cl) < (unsigned)T)
                o_my[(size_t)(step - cl) * 512] = hn + vv;
        }

        gi_my += gstep;
        v_my  += vstep;

        asm volatile("barrier.cluster.arrive.aligned;" ::: "memory");
        asm volatile("barrier.cluster.wait.aligned;"   ::: "memory");
    }
}

// ---------------------------------------------------------------------------
extern "C" void kernel_launch(void* const* d_in, const int* in_sizes, int n_in,
                              void* d_out, int out_size)
{
    const float* V    = (const float*)d_in[0];
    const float* wihf = (const float*)d_in[1];
    const float* whhf = (const float*)d_in[2];
    const float* bihf = (const float*)d_in[3];
    const float* bhhf = (const float*)d_in[4];
    const float* wihb = (const float*)d_in[5];
    const float* whhb = (const float*)d_in[6];
    const float* bihb = (const float*)d_in[7];
    const float* bhhb = (const float*)d_in[8];
    float* out = (float*)d_out;

    const int T  = out_size / (B_ * 512);   // 2028
    const int cl = (S_ - T) / 2;            // 10

    dim3 gg((B_ * S_) / 128, G3_ / 128, 2); // (512, 6, 2)
    gi_gemm<<<gg, 256>>>(V, wihf, wihb, bihf, bihb);

    dim3 gr(4, B_ / 2, 2);                  // (4, 16, 2) — clusters of 4
    rnn_rec<<<gr, 256>>>(whhf, whhb, bhhf, bhhb, V, out, cl, T);
}